// round 1
// baseline (speedup 1.0000x reference)
#include <cuda_runtime.h>
#include <cstdint>
#include <cstddef>

// Problem constants
constexpr int NN  = 8192;   // nodes
constexpr int FIN = 256;    // input features
constexpr int HH  = 64;     // hidden
constexpr int HC  = 128;    // fused hidden columns (h1 | h2)

// Scratch (device globals: allocation-free per harness rules)
__device__ float g_fts[NN * HC];      // [m][j] : j<64 -> seq1@W^T, j>=64 -> seq2@W^T
__device__ float g_h[NN * HC];        // [n][j] : h1 | h2 after bias+PReLU
__device__ float g_part[64 * 64];     // per-slab partial column sums of h1*msk
__device__ float g_mskpart[64];       // per-slab partial msk sums
__device__ float g_wc[64];            // disc_w @ sigmoid(c)

using u64 = unsigned long long;

__device__ __forceinline__ u64 pk2(float x, float y) {
    u64 r; asm("mov.b64 %0, {%1,%2};" : "=l"(r) : "f"(x), "f"(y)); return r;
}
__device__ __forceinline__ float2 unpk(u64 v) {
    float2 r; asm("mov.b64 {%0,%1}, %2;" : "=f"(r.x), "=f"(r.y) : "l"(v)); return r;
}
// Packed dual-FMA: 2x fp32 FMA per instruction on the fma pipe (PTX-only form).
__device__ __forceinline__ void fma2(u64& d, u64 a, u64 b) {
    asm("fma.rn.f32x2 %0, %1, %2, %0;" : "+l"(d) : "l"(a), "l"(b));
}

__device__ __forceinline__ void cpa16(void* dst, const void* src) {
    uint32_t d = (uint32_t)__cvta_generic_to_shared(dst);
    asm volatile("cp.async.ca.shared.global [%0], [%1], 16;\n" :: "r"(d), "l"(src));
}
__device__ __forceinline__ void cpa4(void* dst, const void* src) {
    uint32_t d = (uint32_t)__cvta_generic_to_shared(dst);
    asm volatile("cp.async.ca.shared.global [%0], [%1], 4;\n" :: "r"(d), "l"(src));
}
__device__ __forceinline__ void cp_commit() {
    asm volatile("cp.async.commit_group;\n" ::: "memory");
}
__device__ __forceinline__ void cp_wait0() {
    asm volatile("cp.async.wait_group 0;\n" ::: "memory");
}

// ---------------------------------------------------------------------------
// Kernel 1: fts[m, j] = (j<64 ? seq1 : seq2)[m,:] . fc_w[j&63, :]
// grid 512 blocks x 128 threads, 16 rows per block. fc_w chunk transposed in smem.
// ---------------------------------------------------------------------------
__global__ void __launch_bounds__(128) fts_kernel(
    const float* __restrict__ seq1, const float* __restrict__ seq2,
    const float* __restrict__ fcw) {
    __shared__ float wt[64][64];    // [f_local][h]  (transposed fc_w chunk)
    __shared__ float s1[16][64];    // seq1 rows, f chunk
    __shared__ float s2[16][64];

    const int tid = threadIdx.x;
    const int m0 = blockIdx.x * 16;
    const int jh = tid & 63;

    float acc[16];
#pragma unroll
    for (int r = 0; r < 16; ++r) acc[r] = 0.f;

    for (int fc = 0; fc < 4; ++fc) {
        const int f0 = fc * 64;
        __syncthreads();   // protect smem from previous chunk's readers
        // load+transpose fc_w chunk: fcw[row][f0 + c*4 ..]
        {
            const int row = tid & 63, half = tid >> 6;
#pragma unroll
            for (int p = 0; p < 8; ++p) {
                const int c = half * 8 + p;
                float4 v = *(const float4*)&fcw[row * FIN + f0 + c * 4];
                wt[c * 4 + 0][row] = v.x;
                wt[c * 4 + 1][row] = v.y;
                wt[c * 4 + 2][row] = v.z;
                wt[c * 4 + 3][row] = v.w;
            }
        }
        // load seq chunks
#pragma unroll
        for (int p = 0; p < 2; ++p) {
            const int idx = tid + 128 * p;
            const int r = idx >> 4, c4 = idx & 15;
            *(float4*)&s1[r][c4 * 4] = *(const float4*)&seq1[(size_t)(m0 + r) * FIN + f0 + c4 * 4];
            *(float4*)&s2[r][c4 * 4] = *(const float4*)&seq2[(size_t)(m0 + r) * FIN + f0 + c4 * 4];
        }
        __syncthreads();

        const float (*sp)[64] = (tid < 64) ? s1 : s2;   // uniform per warp
#pragma unroll 4
        for (int f = 0; f < 64; ++f) {
            const float wv = wt[f][jh];
#pragma unroll
            for (int r = 0; r < 16; ++r) acc[r] += sp[r][f] * wv;
        }
    }

#pragma unroll
    for (int r = 0; r < 16; ++r)
        g_fts[(size_t)(m0 + r) * HC + tid] = acc[r];
}

// ---------------------------------------------------------------------------
// Kernel 2 (dominant): h = PReLU(adj @ fts + bias)
// BM=32 x BN=128 tile per block, BK=32, 256 threads, 2x8 micro-tile in f32x2,
// cp.async double-buffered. grid = 256 blocks.
// ---------------------------------------------------------------------------
constexpr int BM = 32, BN = 128, BK = 32;

__global__ void __launch_bounds__(256) gemm_main(
    const float* __restrict__ adj,
    const float* __restrict__ bias,
    const float* __restrict__ alphap) {
    __shared__ __align__(16) float As[2][BK][BM + 2];   // [kk][r], pad 2 -> 8B-aligned pair reads
    __shared__ __align__(16) float Bs[2][BK][BN];

    const int tid = threadIdx.x;
    const int tx = tid & 15;        // n-tile position (8 cols each)
    const int ty = tid >> 4;        // m-tile position (2 rows each)
    const int n0 = blockIdx.x * BM;

    const int a_kk = tid & 31, a_r0 = tid >> 5;
    const int b_r0 = tid >> 5, b_c = (tid & 31) * 4;

    u64 acc[2][4];
#pragma unroll
    for (int i = 0; i < 2; ++i)
#pragma unroll
        for (int j = 0; j < 4; ++j) acc[i][j] = 0ull;

    const int NT = NN / BK;   // 256 k-chunks

    auto prefetch = [&](int t, int s) {
        const int k0 = t * BK;
#pragma unroll
        for (int p = 0; p < 4; ++p)
            cpa4(&As[s][a_kk][a_r0 + p * 8],
                 adj + (size_t)(n0 + a_r0 + p * 8) * NN + k0 + a_kk);
#pragma unroll
        for (int p = 0; p < 4; ++p)
            cpa16(&Bs[s][b_r0 + p * 8][b_c],
                  g_fts + (size_t)(k0 + b_r0 + p * 8) * HC + b_c);
    };

    prefetch(0, 0);
    cp_commit();

    for (int t = 0; t < NT; ++t) {
        const int s = t & 1;
        cp_wait0();
        __syncthreads();
        if (t + 1 < NT) { prefetch(t + 1, s ^ 1); cp_commit(); }

#pragma unroll 8
        for (int kk = 0; kk < BK; ++kk) {
            float2 a = *(const float2*)&As[s][kk][ty * 2];
            u64 A0 = pk2(a.x, a.x);
            u64 A1 = pk2(a.y, a.y);
            ulonglong2 bb0 = *(const ulonglong2*)&Bs[s][kk][tx * 8];
            ulonglong2 bb1 = *(const ulonglong2*)&Bs[s][kk][tx * 8 + 4];
            fma2(acc[0][0], A0, bb0.x); fma2(acc[0][1], A0, bb0.y);
            fma2(acc[0][2], A0, bb1.x); fma2(acc[0][3], A0, bb1.y);
            fma2(acc[1][0], A1, bb0.x); fma2(acc[1][1], A1, bb0.y);
            fma2(acc[1][2], A1, bb1.x); fma2(acc[1][3], A1, bb1.y);
        }
    }

    const float alpha = __ldg(alphap);
#pragma unroll
    for (int m = 0; m < 2; ++m) {
        const int n = n0 + ty * 2 + m;
#pragma unroll
        for (int p = 0; p < 4; ++p) {
            const int col = tx * 8 + p * 2;
            float2 v = unpk(acc[m][p]);
            v.x += __ldg(&bias[col & 63]);
            v.y += __ldg(&bias[(col + 1) & 63]);
            v.x = v.x > 0.f ? v.x : alpha * v.x;
            v.y = v.y > 0.f ? v.y : alpha * v.y;
            *(float2*)&g_h[(size_t)n * HC + col] = v;
        }
    }
}

// ---------------------------------------------------------------------------
// Kernel 3: deterministic partial reduction for c: per-128-row-slab column sums
// of h1 (cols 0..63) weighted by msk, plus msk partial sums. grid 64 x 256.
// ---------------------------------------------------------------------------
__global__ void __launch_bounds__(256) colsum_part(const float* __restrict__ msk) {
    __shared__ float sp[4][64];
    __shared__ float sm[256];
    const int b = blockIdx.x, tid = threadIdx.x;
    const int col = tid & 63, rg = tid >> 6;
    const int base = b * 128;

    float s = 0.f;
#pragma unroll 8
    for (int i = 0; i < 32; ++i) {
        const int n = base + rg + i * 4;
        s += msk[n] * g_h[(size_t)n * HC + col];
    }
    sp[rg][col] = s;
    sm[tid] = (tid < 128) ? msk[base + tid] : 0.f;
    __syncthreads();

    if (tid < 64)
        g_part[b * 64 + tid] = sp[0][tid] + sp[1][tid] + sp[2][tid] + sp[3][tid];

    for (int st = 128; st > 0; st >>= 1) {
        if (tid < st) sm[tid] += sm[tid + st];
        __syncthreads();
    }
    if (tid == 0) g_mskpart[b] = sm[0];
}

// ---------------------------------------------------------------------------
// Kernel 4: c = sigmoid(colsum / msksum); wc = disc_w @ c.  1 block x 64 thr.
// ---------------------------------------------------------------------------
__global__ void make_wc(const float* __restrict__ disc_w) {
    __shared__ float c[64];
    __shared__ float msum;
    const int j = threadIdx.x;

    float s = 0.f;
    for (int b = 0; b < 64; ++b) s += g_part[b * 64 + j];
    if (j == 0) {
        float m = 0.f;
        for (int b = 0; b < 64; ++b) m += g_mskpart[b];
        msum = m;
    }
    __syncthreads();
    float cv = s / msum;
    cv = 1.f / (1.f + expf(-cv));
    c[j] = cv;
    __syncthreads();

    float w = 0.f;
#pragma unroll
    for (int k = 0; k < 64; ++k) w += disc_w[j * 64 + k] * c[k];
    g_wc[j] = w;
}

// ---------------------------------------------------------------------------
// Kernel 5: out[n] = h1[n,:].wc + b ; out[N+n] = h2[n,:].wc + b
// warp per row. grid 1024 x 256.
// ---------------------------------------------------------------------------
__global__ void __launch_bounds__(256) scores(const float* __restrict__ db,
                                              float* __restrict__ out) {
    const int warp = threadIdx.x >> 5, lane = threadIdx.x & 31;
    const int n = blockIdx.x * 8 + warp;
    const float2* hp = (const float2*)(g_h + (size_t)n * HC);
    const float2 w2 = ((const float2*)g_wc)[lane];
    const float2 v1 = hp[lane];
    const float2 v2 = hp[32 + lane];
    float s1 = v1.x * w2.x + v1.y * w2.y;
    float s2 = v2.x * w2.x + v2.y * w2.y;
#pragma unroll
    for (int o = 16; o; o >>= 1) {
        s1 += __shfl_down_sync(0xffffffffu, s1, o);
        s2 += __shfl_down_sync(0xffffffffu, s2, o);
    }
    if (lane == 0) {
        const float bb = __ldg(db);
        out[n] = s1 + bb;
        out[NN + n] = s2 + bb;
    }
}

// ---------------------------------------------------------------------------
// Inputs (metadata order): seq1, seq2, adj, msk, fc_w, gcn_bias, prelu_alpha,
//                          disc_w, disc_b.   Output: [1, 2N] float32.
// ---------------------------------------------------------------------------
extern "C" void kernel_launch(void* const* d_in, const int* in_sizes, int n_in,
                              void* d_out, int out_size) {
    const float* seq1  = (const float*)d_in[0];
    const float* seq2  = (const float*)d_in[1];
    const float* adj   = (const float*)d_in[2];
    const float* msk   = (const float*)d_in[3];
    const float* fcw   = (const float*)d_in[4];
    const float* gbias = (const float*)d_in[5];
    const float* alpha = (const float*)d_in[6];
    const float* discw = (const float*)d_in[7];
    const float* discb = (const float*)d_in[8];
    float* out = (float*)d_out;

    fts_kernel<<<NN / 16, 128>>>(seq1, seq2, fcw);
    gemm_main<<<NN / BM, 256>>>(adj, gbias, alpha);
    colsum_part<<<64, 256>>>(msk);
    make_wc<<<1, 64>>>(discw);
    scores<<<NN / 8, 256>>>(discb, out);
}